// round 2
// baseline (speedup 1.0000x reference)
#include <cuda_runtime.h>
#include <math_constants.h>
#include <cstdint>

// Problem constants
#define DD     1024
#define NB     64     // batch (n_image == n_caption)
#define SS     36     // regions
#define LL     32     // max caption length
#define SMOOTHF 9.0f
#define LAMBDAF 6.0f
#define EPSF   1e-8f

// Derived
#define MROWS  (NB*SS)     // 2304  image rows
#define CROWS  (NB*LL)     // 2048  caption rows
#define NCOLS  (CROWS*2)   // 4096  columns of X (captions | energy)

// Scratch (static device globals; allocation is forbidden)
__device__ float g_E[CROWS * DD];            // energy = captions @ W_g^T   (8.4 MB)
__device__ float g_X[(size_t)MROWS * NCOLS]; // fused  images @ [cap;E]^T   (37.7 MB)
__device__ float g_G[NB * SS * SS];          // per-image Gram matrices
__device__ float g_w1[CROWS];                // caption word norms

// ---------------------------------------------------------------------------
// NT GEMM: C[m,n] = sum_k A[m,k] * Brow(n)[k]; K = 1024 fixed.
// Brow(n) = (n < split) ? B0 + n*K : B1 + (n-split)*K   (split is tile-aligned)
// 128x128 tile, BK=16, 256 threads, 8x8 per thread.
// ---------------------------------------------------------------------------
__global__ __launch_bounds__(256, 2)
void gemm_nt_kernel(const float* __restrict__ A,
                    const float* __restrict__ B0,
                    const float* __restrict__ B1,
                    int split,
                    float* __restrict__ Cmat,
                    int N)
{
    __shared__ float As[16][132];
    __shared__ float Bs[16][132];

    const int tid = threadIdx.x;
    const int m0 = blockIdx.y * 128;
    const int n0 = blockIdx.x * 128;

    const float* Abase = A + (size_t)m0 * DD;
    const float* Bbase = (n0 < split) ? (B0 + (size_t)n0 * DD)
                                      : (B1 + (size_t)(n0 - split) * DD);

    const int lr = tid >> 2;          // 0..63
    const int lc = (tid & 3) * 4;     // 0,4,8,12
    const int tx = tid & 15;
    const int ty = tid >> 4;

    float acc[8][8];
#pragma unroll
    for (int i = 0; i < 8; i++)
#pragma unroll
        for (int j = 0; j < 8; j++) acc[i][j] = 0.f;

    for (int k0 = 0; k0 < DD; k0 += 16) {
        float4 a0 = *(const float4*)(Abase + (size_t)lr        * DD + k0 + lc);
        float4 a1 = *(const float4*)(Abase + (size_t)(lr + 64) * DD + k0 + lc);
        float4 b0 = *(const float4*)(Bbase + (size_t)lr        * DD + k0 + lc);
        float4 b1 = *(const float4*)(Bbase + (size_t)(lr + 64) * DD + k0 + lc);

        __syncthreads();
        As[lc + 0][lr] = a0.x; As[lc + 1][lr] = a0.y;
        As[lc + 2][lr] = a0.z; As[lc + 3][lr] = a0.w;
        As[lc + 0][lr + 64] = a1.x; As[lc + 1][lr + 64] = a1.y;
        As[lc + 2][lr + 64] = a1.z; As[lc + 3][lr + 64] = a1.w;
        Bs[lc + 0][lr] = b0.x; Bs[lc + 1][lr] = b0.y;
        Bs[lc + 2][lr] = b0.z; Bs[lc + 3][lr] = b0.w;
        Bs[lc + 0][lr + 64] = b1.x; Bs[lc + 1][lr + 64] = b1.y;
        Bs[lc + 2][lr + 64] = b1.z; Bs[lc + 3][lr + 64] = b1.w;
        __syncthreads();

#pragma unroll
        for (int kk = 0; kk < 16; kk++) {
            float af[8], bf[8];
            *(float4*)(af)     = *(const float4*)&As[kk][ty * 8];
            *(float4*)(af + 4) = *(const float4*)&As[kk][ty * 8 + 4];
            *(float4*)(bf)     = *(const float4*)&Bs[kk][tx * 8];
            *(float4*)(bf + 4) = *(const float4*)&Bs[kk][tx * 8 + 4];
#pragma unroll
            for (int i = 0; i < 8; i++)
#pragma unroll
                for (int j = 0; j < 8; j++)
                    acc[i][j] += af[i] * bf[j];
        }
    }

#pragma unroll
    for (int i = 0; i < 8; i++) {
        float* crow = Cmat + (size_t)(m0 + ty * 8 + i) * N + n0 + tx * 8;
        *(float4*)(crow)     = make_float4(acc[i][0], acc[i][1], acc[i][2], acc[i][3]);
        *(float4*)(crow + 4) = make_float4(acc[i][4], acc[i][5], acc[i][6], acc[i][7]);
    }
}

// ---------------------------------------------------------------------------
// Per-image Gram matrix: G[b][s][s'] = img[b,s,:] . img[b,s',:]
// ---------------------------------------------------------------------------
__global__ void gram_kernel(const float* __restrict__ images)
{
    __shared__ float T[SS][65];
    const int b = blockIdx.x;
    const int tid = threadIdx.x;  // 256

    float acc[6] = {0.f, 0.f, 0.f, 0.f, 0.f, 0.f};

    for (int d0 = 0; d0 < DD; d0 += 64) {
        __syncthreads();
        for (int i = tid; i < SS * 64; i += 256) {
            int r = i / 64, c = i % 64;
            T[r][c] = images[((size_t)b * SS + r) * DD + d0 + c];
        }
        __syncthreads();
#pragma unroll
        for (int pi = 0; pi < 6; pi++) {
            int p = tid + pi * 256;
            if (p < SS * SS) {
                int s = p / SS, s2 = p % SS;
                float sum = 0.f;
#pragma unroll
                for (int k = 0; k < 64; k++) sum += T[s][k] * T[s2][k];
                acc[pi] += sum;
            }
        }
    }
#pragma unroll
    for (int pi = 0; pi < 6; pi++) {
        int p = tid + pi * 256;
        if (p < SS * SS) g_G[b * SS * SS + p] = acc[pi];
    }
}

// ---------------------------------------------------------------------------
// Caption word norms: g_w1[r] = ||captions_flat[r,:]||
// ---------------------------------------------------------------------------
__global__ void w1_kernel(const float* __restrict__ captions)
{
    const int row = blockIdx.x * 8 + (threadIdx.x >> 5);
    const int lane = threadIdx.x & 31;
    const float* p = captions + (size_t)row * DD;
    float s = 0.f;
    for (int k = lane; k < DD; k += 32) { float v = p[k]; s += v * v; }
#pragma unroll
    for (int o = 16; o; o >>= 1) s += __shfl_xor_sync(0xffffffffu, s, o);
    if (lane == 0) g_w1[row] = sqrtf(s);
}

// ---------------------------------------------------------------------------
// Epilogue: one block per (caption i, image b) pair. 128 threads.
// ---------------------------------------------------------------------------
__global__ __launch_bounds__(128)
void epilogue_kernel(const int* __restrict__ cap_lens, float* __restrict__ out)
{
    const int i = blockIdx.x;   // caption
    const int b = blockIdx.y;   // image

    __shared__ float sA[SS][LL];   // attn, later softmax probs p[s][l]
    __shared__ float sC[SS][LL];   // cap . img
    __shared__ float sQ[SS][LL];   // G @ p
    __shared__ float sG[SS][SS];
    __shared__ float snorm[SS];

    const int tid = threadIdx.x;
    const int len = cap_lens[i];

    for (int p = tid; p < SS * SS; p += 128)
        sG[p / SS][p % SS] = g_G[b * SS * SS + p];

    for (int p = tid; p < SS * LL; p += 128) {
        int s = p / LL, l = p % LL;
        size_t base = ((size_t)(b * SS + s)) * NCOLS;
        float a = g_X[base + CROWS + i * LL + l];     // images . energy
        a = (a > 0.f) ? a : 0.1f * a;                 // LeakyReLU(0.1)
        if (l >= len) a = 0.f;                        // word mask
        sA[s][l] = a;
        sC[s][l] = g_X[base + i * LL + l];            // cap . img
    }
    __syncthreads();

    // l2 norm across words per (s)
    if (tid < SS) {
        float s2 = 0.f;
#pragma unroll
        for (int l = 0; l < LL; l++) { float v = sA[tid][l]; s2 += v * v; }
        snorm[tid] = 1.f / (sqrtf(s2) + EPSF);
    }
    __syncthreads();

    // softmax over regions (s) per word column l
    if (tid < LL) {
        const int l = tid;
        float vals[SS];
        float m = -CUDART_INF_F;
#pragma unroll
        for (int s = 0; s < SS; s++) {
            float v = sA[s][l] * snorm[s] * SMOOTHF;
            vals[s] = v;
            m = fmaxf(m, v);
        }
        float sum = 0.f;
#pragma unroll
        for (int s = 0; s < SS; s++) {
            float e = expf(vals[s] - m);
            vals[s] = e;
            sum += e;
        }
        float inv = 1.f / sum;
#pragma unroll
        for (int s = 0; s < SS; s++) sA[s][l] = vals[s] * inv;
    }
    __syncthreads();

    // q[s][l] = sum_{s'} G[s][s'] * p[s'][l]
    for (int p = tid; p < SS * LL; p += 128) {
        int s = p / LL, l = p % LL;
        float sum = 0.f;
#pragma unroll
        for (int s2 = 0; s2 < SS; s2++) sum += sG[s][s2] * sA[s2][l];
        sQ[s][l] = sum;
    }
    __syncthreads();

    // cosine sim + LogSumExp over valid words (warp 0)
    if (tid < LL) {
        const int l = tid;
        float w12 = 0.f, w2q = 0.f;
#pragma unroll
        for (int s = 0; s < SS; s++) {
            float p = sA[s][l];
            w12 += p * sC[s][l];
            w2q += p * sQ[s][l];
        }
        float w2 = sqrtf(fmaxf(w2q, 0.f));
        float w1 = g_w1[i * LL + l];
        float r = w12 / fmaxf(w1 * w2, EPSF);

        float z = (l < len) ? r * LAMBDAF : -CUDART_INF_F;
        float m = z;
#pragma unroll
        for (int o = 16; o; o >>= 1) m = fmaxf(m, __shfl_xor_sync(0xffffffffu, m, o));
        float e = (l < len) ? expf(z - m) : 0.f;
#pragma unroll
        for (int o = 16; o; o >>= 1) e += __shfl_xor_sync(0xffffffffu, e, o);
        if (l == 0) out[b * NB + i] = (logf(e) + m) / LAMBDAF;
    }
}

// ---------------------------------------------------------------------------
extern "C" void kernel_launch(void* const* d_in, const int* in_sizes, int n_in,
                              void* d_out, int out_size)
{
    const float* images   = (const float*)d_in[0];  // (64, 36, 1024)
    const float* captions = (const float*)d_in[1];  // (64, 32, 1024)
    const int*   cap_lens = (const int*)  d_in[2];  // (64,)
    const float* W_g      = (const float*)d_in[3];  // (1024, 1024)
    float* out = (float*)d_out;                     // (64, 64)

    float *pE, *pX;
    cudaGetSymbolAddress((void**)&pE, g_E);
    cudaGetSymbolAddress((void**)&pX, g_X);

    // 1) E = captions @ W_g^T    (2048 x 1024 x 1024)
    {
        dim3 grid(DD / 128, CROWS / 128);
        gemm_nt_kernel<<<grid, 256>>>(captions, W_g, W_g, 1 << 30, pE, DD);
    }
    // 2) X = images @ [captions ; E]^T   (2304 x 4096 x 1024)
    {
        dim3 grid(NCOLS / 128, MROWS / 128);
        gemm_nt_kernel<<<grid, 256>>>(images, captions, pE, CROWS, pX, NCOLS);
    }
    // 3) Gram matrices + caption norms (independent of 1/2 but stream-ordered; cheap)
    gram_kernel<<<NB, 256>>>(images);
    w1_kernel<<<CROWS / 8, 256>>>(captions);

    // 4) epilogue: (caption i, image b) pairs
    {
        dim3 grid(NB, NB);
        epilogue_kernel<<<grid, 128>>>(cap_lens, out);
    }
}

// round 4
// speedup vs baseline: 1.6467x; 1.6467x over previous
#include <cuda_runtime.h>
#include <cuda_bf16.h>
#include <math_constants.h>
#include <cstdint>

// Problem constants
#define DD     1024
#define NB     64
#define SS     36
#define LL     32
#define SMOOTHF 9.0f
#define LAMBDAF 6.0f
#define EPSF   1e-8f

#define MROWS  (NB*SS)       // 2304 image rows
#define CROWS  (NB*LL)       // 2048 caption rows
#define AROWS  (2*MROWS)     // 4608 = [images ; Y]
#define KSPLIT 3072          // K after [hi|lo|hi] concat
#define XCOLS  CROWS         // 2048

// GEMM tile config (mma.sync path — base ISA, works on sm_103 without 'a')
#define BM 128
#define BN 128
#define BK 64                        // bf16 elems per chunk = 128 B rows
#define NCHUNK (KSPLIT / BK)         // 48
#define NSTAGE 3
#define AB_BYTES (BM * 128)          // 16 KB (BM==BN so same for B)
#define STAGE_BYTES (2 * AB_BYTES)   // 32 KB
#define SMEM_DYN (NSTAGE * STAGE_BYTES + 1024)

// Scratch (static device globals; allocation forbidden)
__device__ __nv_bfloat16 g_A2[(size_t)AROWS * KSPLIT];  // [images-split ; Y-split]
__device__ __nv_bfloat16 g_B2[(size_t)CROWS * KSPLIT];  // captions split
__device__ __nv_bfloat16 g_BW[(size_t)DD   * KSPLIT];   // W_g^T split
__device__ float g_X[(size_t)AROWS * XCOLS];            // fused GEMM output fp32
__device__ float g_G[NB * SS * SS];
__device__ float g_w1[CROWS];

// ---------------------------------------------------------------------------
// PTX helpers (base-ISA only: cp.async, ldmatrix, mma.sync)
// ---------------------------------------------------------------------------
__device__ __forceinline__ uint32_t smem_u32(const void* p) {
    uint32_t a;
    asm("{ .reg .u64 t; cvta.to.shared.u64 t, %1; cvt.u32.u64 %0, t; }" : "=r"(a) : "l"(p));
    return a;
}
#define CP_ASYNC16(dst, src) \
    asm volatile("cp.async.cg.shared.global [%0], [%1], 16;\n" :: "r"(dst), "l"(src))
#define CP_COMMIT() asm volatile("cp.async.commit_group;\n" ::: "memory")
#define CP_WAIT(n)  asm volatile("cp.async.wait_group %0;\n" :: "n"(n) : "memory")

__device__ __forceinline__ void ldsm4(uint32_t* r, uint32_t addr) {
    asm volatile("ldmatrix.sync.aligned.m8n8.x4.shared.b16 {%0,%1,%2,%3}, [%4];"
                 : "=r"(r[0]), "=r"(r[1]), "=r"(r[2]), "=r"(r[3]) : "r"(addr));
}
__device__ __forceinline__ void mma16816(float* c, const uint32_t* a,
                                         uint32_t b0, uint32_t b1) {
    asm volatile("mma.sync.aligned.m16n8k16.row.col.f32.bf16.bf16.f32 "
                 "{%0,%1,%2,%3}, {%4,%5,%6,%7}, {%8,%9}, {%0,%1,%2,%3};"
                 : "+f"(c[0]), "+f"(c[1]), "+f"(c[2]), "+f"(c[3])
                 : "r"(a[0]), "r"(a[1]), "r"(a[2]), "r"(a[3]), "r"(b0), "r"(b1));
}
// SW128 swizzle for 128B rows: off ^ ((off>>3)&0x70); with off=row*128+seg (seg<128):
// = row*128 + (seg ^ ((row&7)<<4))
__device__ __forceinline__ uint32_t swz(int row, int seg) {
    return (uint32_t)(row * 128 + (seg ^ ((row & 7) << 4)));
}

// ---------------------------------------------------------------------------
// Split kernels: fp32 -> bf16 hi/lo, K-concatenated layouts
// A-side pattern: [hi | lo | hi]   (loOff=1024, dupOff=2048)
// B-side pattern: [hi | hi | lo]   (loOff=2048, dupOff=1024)
// ---------------------------------------------------------------------------
__global__ void split_rows_kernel(const float* __restrict__ src, __nv_bfloat16* __restrict__ dst,
                                  int loOff, int dupOff)
{
    int idx = blockIdx.x * 256 + threadIdx.x;
    int row = idx >> 10, col = idx & 1023;
    float f = src[idx];
    __nv_bfloat16 hi = __float2bfloat16(f);
    __nv_bfloat16 lo = __float2bfloat16(f - __bfloat162float(hi));
    size_t r = (size_t)row * KSPLIT;
    dst[r + col] = hi;
    dst[r + loOff + col] = lo;
    dst[r + dupOff + col] = hi;
}

// W_g transpose + split: g_BW[n][hi|hi|lo] with B[n][k] = W_g[k][n]
__global__ void split_w_kernel(const float* __restrict__ W)
{
    __shared__ float t[32][33];
    int k0 = blockIdx.y * 32, n0 = blockIdx.x * 32;
    int tx = threadIdx.x, ty = threadIdx.y;
    t[ty][tx] = W[(size_t)(k0 + ty) * DD + n0 + tx];
    __syncthreads();
    float f = t[tx][ty];                       // = W[k0+tx][n0+ty]
    __nv_bfloat16 hi = __float2bfloat16(f);
    __nv_bfloat16 lo = __float2bfloat16(f - __bfloat162float(hi));
    size_t r = (size_t)(n0 + ty) * KSPLIT;
    g_BW[r + k0 + tx] = hi;
    g_BW[r + 1024 + k0 + tx] = hi;
    g_BW[r + 2048 + k0 + tx] = lo;
}

// ---------------------------------------------------------------------------
// HMMA NT GEMM: C[m,n] = sum_k A[m,k]*B[n,k], K = KSPLIT.
// 128x128 block tile, 8 warps (4m x 2n), warp tile 32x64, BK=64, 3-stage cp.async.
// mode 0: write fp32 C (ldc). mode 1: write split bf16 rows [hi|lo|hi] into Aout.
// ---------------------------------------------------------------------------
__global__ __launch_bounds__(256)
void gemm_mma_kernel(const __nv_bfloat16* __restrict__ A,
                     const __nv_bfloat16* __restrict__ B,
                     float* __restrict__ C,
                     __nv_bfloat16* __restrict__ Aout,
                     int mode, int ldc)
{
    extern __shared__ char smem_raw[];
    const uint32_t sbase = (smem_u32(smem_raw) + 1023u) & ~1023u;

    const int tid = threadIdx.x;
    const int wid = tid >> 5, lane = tid & 31;
    const int wm = wid >> 1;          // 0..3 (m)
    const int wn = wid & 1;           // 0..1 (n)
    const size_t arow0 = (size_t)blockIdx.y * BM;
    const size_t brow0 = (size_t)blockIdx.x * BN;

    const int lr = lane & 15;             // ldmatrix source row within 16
    const int lseg = (lane >> 4) * 16;    // 0 or 16 bytes (k-halves)

    float acc[2][8][4];
#pragma unroll
    for (int t = 0; t < 2; t++)
#pragma unroll
        for (int j = 0; j < 8; j++)
#pragma unroll
            for (int e = 0; e < 4; e++) acc[t][j][e] = 0.f;

    // cp.async loader: each thread moves 4 x 16B for A and 4 x 16B for B.
    const char* Abase = (const char*)(A + arow0 * KSPLIT);
    const char* Bbase = (const char*)(B + brow0 * KSPLIT);
    auto load_chunk = [&](int c, int s) {
        const uint32_t sA = sbase + s * STAGE_BYTES;
        const uint32_t sB = sA + AB_BYTES;
        const size_t cb = (size_t)c * 128;   // byte offset of chunk in each row
#pragma unroll
        for (int i = 0; i < 4; i++) {
            int p = tid + i * 256;           // 0..1023
            int r = p >> 3, seg = (p & 7) * 16;
            CP_ASYNC16(sA + swz(r, seg), Abase + (size_t)r * (KSPLIT * 2) + cb + seg);
        }
#pragma unroll
        for (int i = 0; i < 4; i++) {
            int p = tid + i * 256;
            int r = p >> 3, seg = (p & 7) * 16;
            CP_ASYNC16(sB + swz(r, seg), Bbase + (size_t)r * (KSPLIT * 2) + cb + seg);
        }
        CP_COMMIT();
    };

    auto compute_chunk = [&](int s) {
        const uint32_t sA = sbase + s * STAGE_BYTES;
        const uint32_t sB = sA + AB_BYTES;
#pragma unroll
        for (int kk = 0; kk < 4; kk++) {
            uint32_t af[2][4], bf4[4][4];
#pragma unroll
            for (int t = 0; t < 2; t++) {
                int row = wm * 32 + t * 16 + lr;
                ldsm4(af[t], sA + swz(row, kk * 32 + lseg));
            }
#pragma unroll
            for (int p = 0; p < 4; p++) {
                int row = wn * 64 + p * 16 + lr;
                ldsm4(bf4[p], sB + swz(row, kk * 32 + lseg));
            }
#pragma unroll
            for (int t = 0; t < 2; t++)
#pragma unroll
                for (int j = 0; j < 8; j++) {
                    int p = j >> 1, sel = j & 1;
                    mma16816(acc[t][j], af[t], bf4[p][sel], bf4[p][sel + 2]);
                }
        }
    };

    load_chunk(0, 0);
    load_chunk(1, 1);

    for (int c = 0; c < NCHUNK; c++) {
        if (c + 1 < NCHUNK) { CP_WAIT(1); } else { CP_WAIT(0); }
        __syncthreads();
        if (c + 2 < NCHUNK) load_chunk(c + 2, (c + 2) % NSTAGE);
        compute_chunk(c % NSTAGE);
    }

    // Epilogue. C-frag mapping: lane l -> rows (l>>2, l>>2+8), cols 2*(l&3)+{0,1}.
    const int r0 = lane >> 2;
    const int cb2 = 2 * (lane & 3);
    if (mode == 0) {
#pragma unroll
        for (int t = 0; t < 2; t++) {
#pragma unroll
            for (int j = 0; j < 8; j++) {
                size_t row = arow0 + wm * 32 + t * 16 + r0;
                size_t col = brow0 + wn * 64 + j * 8 + cb2;
                *(float2*)(C + row * ldc + col)       = make_float2(acc[t][j][0], acc[t][j][1]);
                *(float2*)(C + (row + 8) * ldc + col) = make_float2(acc[t][j][2], acc[t][j][3]);
            }
        }
    } else {
#pragma unroll
        for (int t = 0; t < 2; t++) {
#pragma unroll
            for (int j = 0; j < 8; j++) {
                int col = (int)brow0 + wn * 64 + j * 8 + cb2;   // < 1024
#pragma unroll
                for (int h = 0; h < 2; h++) {
                    size_t row = arow0 + wm * 32 + t * 16 + r0 + h * 8;
                    __nv_bfloat16* dr = Aout + row * KSPLIT;
                    float f0 = acc[t][j][2 * h], f1 = acc[t][j][2 * h + 1];
                    __nv_bfloat16 h0 = __float2bfloat16(f0);
                    __nv_bfloat16 h1 = __float2bfloat16(f1);
                    __nv_bfloat16 l0 = __float2bfloat16(f0 - __bfloat162float(h0));
                    __nv_bfloat16 l1 = __float2bfloat16(f1 - __bfloat162float(h1));
                    __nv_bfloat162 hv; hv.x = h0; hv.y = h1;
                    __nv_bfloat162 lv; lv.x = l0; lv.y = l1;
                    *(__nv_bfloat162*)(dr + col)        = hv;
                    *(__nv_bfloat162*)(dr + 1024 + col) = lv;
                    *(__nv_bfloat162*)(dr + 2048 + col) = hv;
                }
            }
        }
    }
}

// ---------------------------------------------------------------------------
// Per-image Gram matrix
// ---------------------------------------------------------------------------
__global__ void gram_kernel(const float* __restrict__ images)
{
    __shared__ float T[SS][65];
    const int b = blockIdx.x;
    const int tid = threadIdx.x;
    float acc[6] = {0.f, 0.f, 0.f, 0.f, 0.f, 0.f};
    for (int d0 = 0; d0 < DD; d0 += 64) {
        __syncthreads();
        for (int i = tid; i < SS * 64; i += 256) {
            int r = i / 64, c = i % 64;
            T[r][c] = images[((size_t)b * SS + r) * DD + d0 + c];
        }
        __syncthreads();
#pragma unroll
        for (int pi = 0; pi < 6; pi++) {
            int p = tid + pi * 256;
            if (p < SS * SS) {
                int s = p / SS, s2 = p % SS;
                float sum = 0.f;
#pragma unroll
                for (int k = 0; k < 64; k++) sum += T[s][k] * T[s2][k];
                acc[pi] += sum;
            }
        }
    }
#pragma unroll
    for (int pi = 0; pi < 6; pi++) {
        int p = tid + pi * 256;
        if (p < SS * SS) g_G[b * SS * SS + p] = acc[pi];
    }
}

__global__ void w1_kernel(const float* __restrict__ captions)
{
    const int row = blockIdx.x * 8 + (threadIdx.x >> 5);
    const int lane = threadIdx.x & 31;
    const float* p = captions + (size_t)row * DD;
    float s = 0.f;
    for (int k = lane; k < DD; k += 32) { float v = p[k]; s += v * v; }
#pragma unroll
    for (int o = 16; o; o >>= 1) s += __shfl_xor_sync(0xffffffffu, s, o);
    if (lane == 0) g_w1[row] = sqrtf(s);
}

// ---------------------------------------------------------------------------
// Final epilogue: one block per (caption i, image b)
// ---------------------------------------------------------------------------
__global__ __launch_bounds__(128)
void epilogue_kernel(const int* __restrict__ cap_lens, float* __restrict__ out)
{
    const int i = blockIdx.x;
    const int b = blockIdx.y;

    __shared__ float sA[SS][LL];
    __shared__ float sC[SS][LL];
    __shared__ float sQ[SS][LL];
    __shared__ float sG[SS][SS];
    __shared__ float snorm[SS];

    const int tid = threadIdx.x;
    const int len = cap_lens[i];

    for (int p = tid; p < SS * SS; p += 128)
        sG[p / SS][p % SS] = g_G[b * SS * SS + p];

    for (int p = tid; p < SS * LL; p += 128) {
        int s = p / LL, l = p % LL;
        size_t col = (size_t)i * LL + l;
        float a = g_X[(size_t)(MROWS + b * SS + s) * XCOLS + col];  // attn logits (Y.cap)
        a = (a > 0.f) ? a : 0.1f * a;
        if (l >= len) a = 0.f;
        sA[s][l] = a;
        sC[s][l] = g_X[(size_t)(b * SS + s) * XCOLS + col];          // cap . img
    }
    __syncthreads();

    if (tid < SS) {
        float s2 = 0.f;
#pragma unroll
        for (int l = 0; l < LL; l++) { float v = sA[tid][l]; s2 += v * v; }
        snorm[tid] = 1.f / (sqrtf(s2) + EPSF);
    }
    __syncthreads();

    if (tid < LL) {
        const int l = tid;
        float vals[SS];
        float m = -CUDART_INF_F;
#pragma unroll
        for (int s = 0; s < SS; s++) {
            float v = sA[s][l] * snorm[s] * SMOOTHF;
            vals[s] = v;
            m = fmaxf(m, v);
        }
        float sum = 0.f;
#pragma unroll
        for (int s = 0; s < SS; s++) {
            float e = expf(vals[s] - m);
            vals[s] = e;
            sum += e;
        }
        float inv = 1.f / sum;
#pragma unroll
        for (int s = 0; s < SS; s++) sA[s][l] = vals[s] * inv;
    }
    __syncthreads();

    for (int p = tid; p < SS * LL; p += 128) {
        int s = p / LL, l = p % LL;
        float sum = 0.f;
#pragma unroll
        for (int s2 = 0; s2 < SS; s2++) sum += sG[s][s2] * sA[s2][l];
        sQ[s][l] = sum;
    }
    __syncthreads();

    if (tid < LL) {
        const int l = tid;
        float w12 = 0.f, w2q = 0.f;
#pragma unroll
        for (int s = 0; s < SS; s++) {
            float p = sA[s][l];
            w12 += p * sC[s][l];
            w2q += p * sQ[s][l];
        }
        float w2 = sqrtf(fmaxf(w2q, 0.f));
        float w1 = g_w1[i * LL + l];
        float r = w12 / fmaxf(w1 * w2, EPSF);

        float z = (l < len) ? r * LAMBDAF : -CUDART_INF_F;
        float m = z;
#pragma unroll
        for (int o = 16; o; o >>= 1) m = fmaxf(m, __shfl_xor_sync(0xffffffffu, m, o));
        float e = (l < len) ? expf(z - m) : 0.f;
#pragma unroll
        for (int o = 16; o; o >>= 1) e += __shfl_xor_sync(0xffffffffu, e, o);
        if (l == 0) out[b * NB + i] = (logf(e) + m) / LAMBDAF;
    }
}

// ---------------------------------------------------------------------------
extern "C" void kernel_launch(void* const* d_in, const int* in_sizes, int n_in,
                              void* d_out, int out_size)
{
    const float* images   = (const float*)d_in[0];  // (64, 36, 1024)
    const float* captions = (const float*)d_in[1];  // (64, 32, 1024)
    const int*   cap_lens = (const int*)  d_in[2];  // (64,)
    const float* W_g      = (const float*)d_in[3];  // (1024, 1024)
    float* out = (float*)d_out;                     // (64, 64)

    __nv_bfloat16 *pA2, *pB2, *pBW;
    float *pX;
    cudaGetSymbolAddress((void**)&pA2, g_A2);
    cudaGetSymbolAddress((void**)&pB2, g_B2);
    cudaGetSymbolAddress((void**)&pBW, g_BW);
    cudaGetSymbolAddress((void**)&pX,  g_X);

    cudaFuncSetAttribute(gemm_mma_kernel, cudaFuncAttributeMaxDynamicSharedMemorySize, SMEM_DYN);

    // 1) Splits
    split_rows_kernel<<<MROWS * DD / 256, 256>>>(images, pA2, 1024, 2048);   // [hi|lo|hi]
    split_rows_kernel<<<CROWS * DD / 256, 256>>>(captions, pB2, 2048, 1024); // [hi|hi|lo]
    {
        dim3 grid(DD / 32, DD / 32);
        split_w_kernel<<<grid, dim3(32, 32)>>>(W_g);
    }

    // 2) GEMM-P: Y = images @ W_g -> split bf16 into g_A2 rows [2304, 4608)
    {
        dim3 grid(DD / BN, MROWS / BM);      // (8, 18)
        gemm_mma_kernel<<<grid, 256, SMEM_DYN>>>(pA2, pBW, nullptr,
                                                 pA2 + (size_t)MROWS * KSPLIT, 1, 0);
    }
    // 3) GEMM-X: X = [images ; Y] @ captions^T  (4608 x 2048, fp32)
    {
        dim3 grid(XCOLS / BN, AROWS / BM);   // (16, 36)
        gemm_mma_kernel<<<grid, 256, SMEM_DYN>>>(pA2, pB2, pX, nullptr, 0, XCOLS);
    }

    // 4) Gram + caption norms
    gram_kernel<<<NB, 256>>>(images);
    w1_kernel<<<CROWS / 8, 256>>>(captions);

    // 5) Final epilogue
    {
        dim3 grid(NB, NB);
        epilogue_kernel<<<grid, 128>>>(cap_lens, out);
    }
}

// round 5
// speedup vs baseline: 1.7438x; 1.0590x over previous
#include <cuda_runtime.h>
#include <cuda_bf16.h>
#include <math_constants.h>
#include <cstdint>

// Problem constants
#define DD     1024
#define NB     64
#define SS     36
#define LL     32
#define SMOOTHF 9.0f
#define LAMBDAF 6.0f
#define EPSF   1e-8f

#define MROWS  (NB*SS)       // 2304 image rows
#define CROWS  (NB*LL)       // 2048 caption rows
#define AROWS  (2*MROWS)     // 4608 = [images ; Y]
#define KSPLIT 3072          // K after [hi|lo|hi] concat
#define XCOLS  CROWS         // 2048

#define BN 128
#define BK 64                        // bf16 elems per chunk = 128 B rows
#define NCHUNK (KSPLIT / BK)         // 48
#define NSTAGE 2

// Scratch (static device globals; allocation forbidden)
__device__ __nv_bfloat16 g_A2[(size_t)AROWS * KSPLIT];  // [images-split ; Y-split]
__device__ __nv_bfloat16 g_B2[(size_t)CROWS * KSPLIT];  // captions split
__device__ __nv_bfloat16 g_BW[(size_t)DD   * KSPLIT];   // W_g^T split
__device__ float g_X[(size_t)AROWS * XCOLS];            // fused GEMM output fp32
__device__ float g_G[NB * SS * SS];
__device__ float g_w1[CROWS];

// ---------------------------------------------------------------------------
// PTX helpers (base-ISA only: cp.async, ldmatrix, mma.sync)
// ---------------------------------------------------------------------------
__device__ __forceinline__ uint32_t smem_u32(const void* p) {
    uint32_t a;
    asm("{ .reg .u64 t; cvta.to.shared.u64 t, %1; cvt.u32.u64 %0, t; }" : "=r"(a) : "l"(p));
    return a;
}
#define CP_ASYNC16(dst, src) \
    asm volatile("cp.async.cg.shared.global [%0], [%1], 16;\n" :: "r"(dst), "l"(src))
#define CP_COMMIT() asm volatile("cp.async.commit_group;\n" ::: "memory")
#define CP_WAIT(n)  asm volatile("cp.async.wait_group %0;\n" :: "n"(n) : "memory")

__device__ __forceinline__ void ldsm4(uint32_t* r, uint32_t addr) {
    asm volatile("ldmatrix.sync.aligned.m8n8.x4.shared.b16 {%0,%1,%2,%3}, [%4];"
                 : "=r"(r[0]), "=r"(r[1]), "=r"(r[2]), "=r"(r[3]) : "r"(addr));
}
__device__ __forceinline__ void mma16816(float* c, const uint32_t* a,
                                         uint32_t b0, uint32_t b1) {
    asm volatile("mma.sync.aligned.m16n8k16.row.col.f32.bf16.bf16.f32 "
                 "{%0,%1,%2,%3}, {%4,%5,%6,%7}, {%8,%9}, {%0,%1,%2,%3};"
                 : "+f"(c[0]), "+f"(c[1]), "+f"(c[2]), "+f"(c[3])
                 : "r"(a[0]), "r"(a[1]), "r"(a[2]), "r"(a[3]), "r"(b0), "r"(b1));
}
// SW128 swizzle for 128B rows
__device__ __forceinline__ uint32_t swz(int row, int seg) {
    return (uint32_t)(row * 128 + (seg ^ ((row & 7) << 4)));
}

// ---------------------------------------------------------------------------
// Split kernels
// A-side pattern: [hi | lo | hi]; B-side pattern: [hi | hi | lo]
// ---------------------------------------------------------------------------
__global__ void split_rows_kernel(const float* __restrict__ src, __nv_bfloat16* __restrict__ dst,
                                  int loOff, int dupOff)
{
    int idx = blockIdx.x * 256 + threadIdx.x;
    int row = idx >> 10, col = idx & 1023;
    float f = src[idx];
    __nv_bfloat16 hi = __float2bfloat16(f);
    __nv_bfloat16 lo = __float2bfloat16(f - __bfloat162float(hi));
    size_t r = (size_t)row * KSPLIT;
    dst[r + col] = hi;
    dst[r + loOff + col] = lo;
    dst[r + dupOff + col] = hi;
}

__global__ void split_w_kernel(const float* __restrict__ W)
{
    __shared__ float t[32][33];
    int k0 = blockIdx.y * 32, n0 = blockIdx.x * 32;
    int tx = threadIdx.x, ty = threadIdx.y;
    t[ty][tx] = W[(size_t)(k0 + ty) * DD + n0 + tx];
    __syncthreads();
    float f = t[tx][ty];                       // = W[k0+tx][n0+ty]
    __nv_bfloat16 hi = __float2bfloat16(f);
    __nv_bfloat16 lo = __float2bfloat16(f - __bfloat162float(hi));
    size_t r = (size_t)(n0 + ty) * KSPLIT;
    g_BW[r + k0 + tx] = hi;
    g_BW[r + 1024 + k0 + tx] = hi;
    g_BW[r + 2048 + k0 + tx] = lo;
}

// ---------------------------------------------------------------------------
// HMMA NT GEMM: C[m,n] = sum_k A[m,k]*B[n,k], K = KSPLIT, BN=128 fixed.
// Templated on tile height / warp layout. Warp tile 32x64.
// mode 0: write fp32 C (ldc). mode 1: write split bf16 rows [hi|lo|hi] into Aout.
// ---------------------------------------------------------------------------
template<int BMt, int WARPS_M, int MIN_CTAS>
__global__ __launch_bounds__(WARPS_M * 2 * 32, MIN_CTAS)
void gemm_mma_kernel(const __nv_bfloat16* __restrict__ A,
                     const __nv_bfloat16* __restrict__ B,
                     float* __restrict__ C,
                     __nv_bfloat16* __restrict__ Aout,
                     int mode, int ldc)
{
    constexpr int THREADS = WARPS_M * 2 * 32;
    constexpr int A_BYTES = BMt * 128;
    constexpr int B_BYTES = BN * 128;
    constexpr int STAGE_BYTES = A_BYTES + B_BYTES;
    constexpr int A_IT = BMt * 8 / THREADS;
    constexpr int B_IT = BN * 8 / THREADS;

    extern __shared__ char smem_raw[];
    const uint32_t sbase = (smem_u32(smem_raw) + 1023u) & ~1023u;

    const int tid = threadIdx.x;
    const int wid = tid >> 5, lane = tid & 31;
    const int wm = wid >> 1;          // 0..WARPS_M-1 (m)
    const int wn = wid & 1;           // 0..1 (n)
    const size_t arow0 = (size_t)blockIdx.y * BMt;
    const size_t brow0 = (size_t)blockIdx.x * BN;

    const int lr = lane & 15;
    const int lseg = (lane >> 4) * 16;

    float acc[2][8][4];
#pragma unroll
    for (int t = 0; t < 2; t++)
#pragma unroll
        for (int j = 0; j < 8; j++)
#pragma unroll
            for (int e = 0; e < 4; e++) acc[t][j][e] = 0.f;

    const char* Abase = (const char*)(A + arow0 * KSPLIT);
    const char* Bbase = (const char*)(B + brow0 * KSPLIT);
    auto load_chunk = [&](int c, int s) {
        const uint32_t sA = sbase + s * STAGE_BYTES;
        const uint32_t sB = sA + A_BYTES;
        const size_t cb = (size_t)c * 128;
#pragma unroll
        for (int i = 0; i < A_IT; i++) {
            int p = tid + i * THREADS;
            int r = p >> 3, seg = (p & 7) * 16;
            CP_ASYNC16(sA + swz(r, seg), Abase + (size_t)r * (KSPLIT * 2) + cb + seg);
        }
#pragma unroll
        for (int i = 0; i < B_IT; i++) {
            int p = tid + i * THREADS;
            int r = p >> 3, seg = (p & 7) * 16;
            CP_ASYNC16(sB + swz(r, seg), Bbase + (size_t)r * (KSPLIT * 2) + cb + seg);
        }
        CP_COMMIT();
    };

    auto compute_chunk = [&](int s) {
        const uint32_t sA = sbase + s * STAGE_BYTES;
        const uint32_t sB = sA + A_BYTES;
#pragma unroll
        for (int kk = 0; kk < 4; kk++) {
            uint32_t af[2][4], bf4[4][4];
#pragma unroll
            for (int t = 0; t < 2; t++) {
                int row = wm * 32 + t * 16 + lr;
                ldsm4(af[t], sA + swz(row, kk * 32 + lseg));
            }
#pragma unroll
            for (int p = 0; p < 4; p++) {
                int row = wn * 64 + p * 16 + lr;
                ldsm4(bf4[p], sB + swz(row, kk * 32 + lseg));
            }
#pragma unroll
            for (int t = 0; t < 2; t++)
#pragma unroll
                for (int j = 0; j < 8; j++) {
                    int p = j >> 1, sel = j & 1;
                    mma16816(acc[t][j], af[t], bf4[p][sel], bf4[p][sel + 2]);
                }
        }
    };

    load_chunk(0, 0);

    for (int c = 0; c < NCHUNK; c++) {
        if (c + 1 < NCHUNK) { load_chunk(c + 1, (c + 1) & 1); CP_WAIT(1); }
        else                { CP_WAIT(0); }
        __syncthreads();
        compute_chunk(c & 1);
        __syncthreads();
    }

    // Epilogue. C-frag mapping: lane l -> rows (l>>2, l>>2+8), cols 2*(l&3)+{0,1}.
    const int r0 = lane >> 2;
    const int cb2 = 2 * (lane & 3);
    if (mode == 0) {
#pragma unroll
        for (int t = 0; t < 2; t++) {
#pragma unroll
            for (int j = 0; j < 8; j++) {
                size_t row = arow0 + wm * 32 + t * 16 + r0;
                size_t col = brow0 + wn * 64 + j * 8 + cb2;
                *(float2*)(C + row * ldc + col)       = make_float2(acc[t][j][0], acc[t][j][1]);
                *(float2*)(C + (row + 8) * ldc + col) = make_float2(acc[t][j][2], acc[t][j][3]);
            }
        }
    } else {
#pragma unroll
        for (int t = 0; t < 2; t++) {
#pragma unroll
            for (int j = 0; j < 8; j++) {
                int col = (int)brow0 + wn * 64 + j * 8 + cb2;   // < 1024
#pragma unroll
                for (int h = 0; h < 2; h++) {
                    size_t row = arow0 + wm * 32 + t * 16 + r0 + h * 8;
                    __nv_bfloat16* dr = Aout + row * KSPLIT;
                    float f0 = acc[t][j][2 * h], f1 = acc[t][j][2 * h + 1];
                    __nv_bfloat16 h0 = __float2bfloat16(f0);
                    __nv_bfloat16 h1 = __float2bfloat16(f1);
                    __nv_bfloat16 l0 = __float2bfloat16(f0 - __bfloat162float(h0));
                    __nv_bfloat16 l1 = __float2bfloat16(f1 - __bfloat162float(h1));
                    __nv_bfloat162 hv; hv.x = h0; hv.y = h1;
                    __nv_bfloat162 lv; lv.x = l0; lv.y = l1;
                    *(__nv_bfloat162*)(dr + col)        = hv;
                    *(__nv_bfloat162*)(dr + 1024 + col) = lv;
                    *(__nv_bfloat162*)(dr + 2048 + col) = hv;
                }
            }
        }
    }
}

// ---------------------------------------------------------------------------
// Per-image Gram matrix
// ---------------------------------------------------------------------------
__global__ void gram_kernel(const float* __restrict__ images)
{
    __shared__ float T[SS][65];
    const int b = blockIdx.x;
    const int tid = threadIdx.x;
    float acc[6] = {0.f, 0.f, 0.f, 0.f, 0.f, 0.f};
    for (int d0 = 0; d0 < DD; d0 += 64) {
        __syncthreads();
        for (int i = tid; i < SS * 64; i += 256) {
            int r = i / 64, c = i % 64;
            T[r][c] = images[((size_t)b * SS + r) * DD + d0 + c];
        }
        __syncthreads();
#pragma unroll
        for (int pi = 0; pi < 6; pi++) {
            int p = tid + pi * 256;
            if (p < SS * SS) {
                int s = p / SS, s2 = p % SS;
                float sum = 0.f;
#pragma unroll
                for (int k = 0; k < 64; k++) sum += T[s][k] * T[s2][k];
                acc[pi] += sum;
            }
        }
    }
#pragma unroll
    for (int pi = 0; pi < 6; pi++) {
        int p = tid + pi * 256;
        if (p < SS * SS) g_G[b * SS * SS + p] = acc[pi];
    }
}

__global__ void w1_kernel(const float* __restrict__ captions)
{
    const int row = blockIdx.x * 8 + (threadIdx.x >> 5);
    const int lane = threadIdx.x & 31;
    const float* p = captions + (size_t)row * DD;
    float s = 0.f;
    for (int k = lane; k < DD; k += 32) { float v = p[k]; s += v * v; }
#pragma unroll
    for (int o = 16; o; o >>= 1) s += __shfl_xor_sync(0xffffffffu, s, o);
    if (lane == 0) g_w1[row] = sqrtf(s);
}

// ---------------------------------------------------------------------------
// Final epilogue: one block per (caption i, image b)
// ---------------------------------------------------------------------------
__global__ __launch_bounds__(128)
void epilogue_kernel(const int* __restrict__ cap_lens, float* __restrict__ out)
{
    const int i = blockIdx.x;
    const int b = blockIdx.y;

    __shared__ float sA[SS][LL];
    __shared__ float sC[SS][LL];
    __shared__ float sQ[SS][LL];
    __shared__ float sG[SS][SS];
    __shared__ float snorm[SS];

    const int tid = threadIdx.x;
    const int len = cap_lens[i];

    for (int p = tid; p < SS * SS; p += 128)
        sG[p / SS][p % SS] = g_G[b * SS * SS + p];

    for (int p = tid; p < SS * LL; p += 128) {
        int s = p / LL, l = p % LL;
        size_t col = (size_t)i * LL + l;
        float a = g_X[(size_t)(MROWS + b * SS + s) * XCOLS + col];  // attn logits (Y.cap)
        a = (a > 0.f) ? a : 0.1f * a;
        if (l >= len) a = 0.f;
        sA[s][l] = a;
        sC[s][l] = g_X[(size_t)(b * SS + s) * XCOLS + col];          // cap . img
    }
    __syncthreads();

    if (tid < SS) {
        float s2 = 0.f;
#pragma unroll
        for (int l = 0; l < LL; l++) { float v = sA[tid][l]; s2 += v * v; }
        snorm[tid] = 1.f / (sqrtf(s2) + EPSF);
    }
    __syncthreads();

    if (tid < LL) {
        const int l = tid;
        float vals[SS];
        float m = -CUDART_INF_F;
#pragma unroll
        for (int s = 0; s < SS; s++) {
            float v = sA[s][l] * snorm[s] * SMOOTHF;
            vals[s] = v;
            m = fmaxf(m, v);
        }
        float sum = 0.f;
#pragma unroll
        for (int s = 0; s < SS; s++) {
            float e = expf(vals[s] - m);
            vals[s] = e;
            sum += e;
        }
        float inv = 1.f / sum;
#pragma unroll
        for (int s = 0; s < SS; s++) sA[s][l] = vals[s] * inv;
    }
    __syncthreads();

    for (int p = tid; p < SS * LL; p += 128) {
        int s = p / LL, l = p % LL;
        float sum = 0.f;
#pragma unroll
        for (int s2 = 0; s2 < SS; s2++) sum += sG[s][s2] * sA[s2][l];
        sQ[s][l] = sum;
    }
    __syncthreads();

    if (tid < LL) {
        const int l = tid;
        float w12 = 0.f, w2q = 0.f;
#pragma unroll
        for (int s = 0; s < SS; s++) {
            float p = sA[s][l];
            w12 += p * sC[s][l];
            w2q += p * sQ[s][l];
        }
        float w2 = sqrtf(fmaxf(w2q, 0.f));
        float w1 = g_w1[i * LL + l];
        float r = w12 / fmaxf(w1 * w2, EPSF);

        float z = (l < len) ? r * LAMBDAF : -CUDART_INF_F;
        float m = z;
#pragma unroll
        for (int o = 16; o; o >>= 1) m = fmaxf(m, __shfl_xor_sync(0xffffffffu, m, o));
        float e = (l < len) ? expf(z - m) : 0.f;
#pragma unroll
        for (int o = 16; o; o >>= 1) e += __shfl_xor_sync(0xffffffffu, e, o);
        if (l == 0) out[b * NB + i] = (logf(e) + m) / LAMBDAF;
    }
}

// ---------------------------------------------------------------------------
extern "C" void kernel_launch(void* const* d_in, const int* in_sizes, int n_in,
                              void* d_out, int out_size)
{
    const float* images   = (const float*)d_in[0];  // (64, 36, 1024)
    const float* captions = (const float*)d_in[1];  // (64, 32, 1024)
    const int*   cap_lens = (const int*)  d_in[2];  // (64,)
    const float* W_g      = (const float*)d_in[3];  // (1024, 1024)
    float* out = (float*)d_out;                     // (64, 64)

    __nv_bfloat16 *pA2, *pB2, *pBW;
    float *pX;
    cudaGetSymbolAddress((void**)&pA2, g_A2);
    cudaGetSymbolAddress((void**)&pB2, g_B2);
    cudaGetSymbolAddress((void**)&pBW, g_BW);
    cudaGetSymbolAddress((void**)&pX,  g_X);

    // Dynamic smem: P variant (BM=64): 2*(64+128)*128 + 1024 = 50176
    //               X variant (BM=128): 2*(128+128)*128 + 1024 = 66560
    const int SMEM_P = NSTAGE * (64 + BN) * 128 + 1024;
    const int SMEM_X = NSTAGE * (128 + BN) * 128 + 1024;
    cudaFuncSetAttribute((const void*)gemm_mma_kernel<64, 2, 4>,
                         cudaFuncAttributeMaxDynamicSharedMemorySize, SMEM_P);
    cudaFuncSetAttribute((const void*)gemm_mma_kernel<128, 4, 2>,
                         cudaFuncAttributeMaxDynamicSharedMemorySize, SMEM_X);

    // 1) Splits
    split_rows_kernel<<<MROWS * DD / 256, 256>>>(images, pA2, 1024, 2048);   // [hi|lo|hi]
    split_rows_kernel<<<CROWS * DD / 256, 256>>>(captions, pB2, 2048, 1024); // [hi|hi|lo]
    {
        dim3 grid(DD / 32, DD / 32);
        split_w_kernel<<<grid, dim3(32, 32)>>>(W_g);
    }

    // 2) GEMM-P: Y = images @ W_g -> split bf16 into g_A2 rows [2304, 4608)
    //    BM=64, 128 threads, 4 CTAs/SM, grid (8, 36) = 288
    {
        dim3 grid(DD / BN, MROWS / 64);
        gemm_mma_kernel<64, 2, 4><<<grid, 128, SMEM_P>>>(pA2, pBW, nullptr,
                                                         pA2 + (size_t)MROWS * KSPLIT, 1, 0);
    }
    // 3) GEMM-X: X = [images ; Y] @ captions^T  (4608 x 2048, fp32)
    //    BM=128, 256 threads, 2 CTAs/SM, grid (16, 36) = 576
    {
        dim3 grid(XCOLS / BN, AROWS / 128);
        gemm_mma_kernel<128, 4, 2><<<grid, 256, SMEM_X>>>(pA2, pB2, pX, nullptr, 0, XCOLS);
    }

    // 4) Gram + caption norms
    gram_kernel<<<NB, 256>>>(images);
    w1_kernel<<<CROWS / 8, 256>>>(captions);

    // 5) Final epilogue
    {
        dim3 grid(NB, NB);
        epilogue_kernel<<<grid, 128>>>(cap_lens, out);
    }
}